// round 13
// baseline (speedup 1.0000x reference)
#include <cuda_runtime.h>
#include <cuda_bf16.h>
#include <cstdint>

#define D 128
#define MAX_NODES 100000
#define MAX_EDGES 1600000

// Scratch (no cudaMalloc allowed).
__device__ ushort   g_Whi[D * D];   // bf16 W^T hi: [n][k]
__device__ ushort   g_Wlo[D * D];   // bf16 W^T lo: [n][k]
__device__ int      g_deg[MAX_NODES];
__device__ int      g_off[MAX_NODES + 1];
__device__ int      g_pos[MAX_NODES];
__device__ int      g_bsum[128];
__device__ int2     g_edges[MAX_EDGES];   // {src, __float_as_int(val)}

// ===========================================================================
// Kernel 1 (merged): blocks [0,128) zero degree counters;
//                    blocks [128,192) do W split+transpose.
// ===========================================================================
__global__ void prep_kernel(const float* __restrict__ W, int n) {
    if (blockIdx.x < 128) {
        int i = blockIdx.x * blockDim.x + threadIdx.x;
        int stride = 128 * blockDim.x;
        for (; i < n; i += stride) g_deg[i] = 0;
    } else {
        int i = (blockIdx.x - 128) * blockDim.x + threadIdx.x;
        if (i >= D * D) return;
        int k = i >> 7, nn = i & 127;
        float w = W[i];
        __nv_bfloat16 h = __float2bfloat16(w);
        float r = w - __bfloat162float(h);
        __nv_bfloat16 l = __float2bfloat16(r);
        g_Whi[nn * D + k] = __bfloat16_as_ushort(h);
        g_Wlo[nn * D + k] = __bfloat16_as_ushort(l);
    }
}

// ===========================================================================
// Histogram: 4 edges per thread via int4 load (MLP=4 on the atomics).
// ===========================================================================
__global__ void hist_kernel(const int* __restrict__ erow, int n_edges) {
    int t = blockIdx.x * blockDim.x + threadIdx.x;
    int base = t * 4;
    if (base + 3 < n_edges) {
        int4 r = reinterpret_cast<const int4*>(erow)[t];
        atomicAdd(&g_deg[r.x], 1);
        atomicAdd(&g_deg[r.y], 1);
        atomicAdd(&g_deg[r.z], 1);
        atomicAdd(&g_deg[r.w], 1);
    } else {
        for (int e = base; e < n_edges; e++) atomicAdd(&g_deg[erow[e]], 1);
    }
}

// ===========================================================================
// Scan phase A: per-block (1024 elems) exclusive scan; block sum to g_bsum.
// ===========================================================================
__global__ void scanA_kernel(int n) {
    __shared__ int s[1024];
    int t = threadIdx.x;
    int i = blockIdx.x * 1024 + t;
    int v = (i < n) ? g_deg[i] : 0;
    s[t] = v;
    __syncthreads();
    for (int off = 1; off < 1024; off <<= 1) {
        int u = (t >= off) ? s[t - off] : 0;
        __syncthreads();
        s[t] += u;
        __syncthreads();
    }
    if (i < n) g_off[i] = s[t] - v;       // exclusive within block
    if (t == 1023) g_bsum[blockIdx.x] = s[1023];
}

// ===========================================================================
// Scan phase C: block prefix = sum of bsum[0..bid-1] via shfl-reduction
// (no full scan needed). Last block writes the grand total.
// ===========================================================================
__global__ void scanC_kernel(int nb, int n) {
    __shared__ int spre[4], stot[4];
    int t = threadIdx.x;
    int bid = blockIdx.x;

    int pre = 0, tot = 0;
    if (t < 128) {
        int b = (t < nb) ? g_bsum[t] : 0;
        pre = (t < bid) ? b : 0;
        tot = b;
    }
    #pragma unroll
    for (int o = 16; o > 0; o >>= 1) {
        pre += __shfl_down_sync(0xffffffffu, pre, o);
        tot += __shfl_down_sync(0xffffffffu, tot, o);
    }
    if (t < 128 && (t & 31) == 0) { spre[t >> 5] = pre; stot[t >> 5] = tot; }
    __syncthreads();
    int prefix = spre[0] + spre[1] + spre[2] + spre[3];
    int total  = stot[0] + stot[1] + stot[2] + stot[3];

    int i = bid * 1024 + t;
    if (i < n) {
        int o = g_off[i] + prefix;
        g_off[i] = o;
        g_pos[i] = o;
    }
    if (bid == nb - 1 && t == 0) g_off[n] = total;
}

// ===========================================================================
// Bin edges into CSR order; 4 edges per thread.
// ===========================================================================
__global__ void bin_kernel(const int*   __restrict__ erow,
                           const int*   __restrict__ ecol,
                           const float* __restrict__ evals,
                           int n_edges) {
    int t = blockIdx.x * blockDim.x + threadIdx.x;
    int base = t * 4;
    if (base + 3 < n_edges) {
        int4   rr = reinterpret_cast<const int4*>(erow)[t];
        int4   cc = reinterpret_cast<const int4*>(ecol)[t];
        float4 vv = reinterpret_cast<const float4*>(evals)[t];
        int p0 = atomicAdd(&g_pos[rr.x], 1);
        int p1 = atomicAdd(&g_pos[rr.y], 1);
        int p2 = atomicAdd(&g_pos[rr.z], 1);
        int p3 = atomicAdd(&g_pos[rr.w], 1);
        g_edges[p0] = make_int2(cc.x, __float_as_int(vv.x));
        g_edges[p1] = make_int2(cc.y, __float_as_int(vv.y));
        g_edges[p2] = make_int2(cc.z, __float_as_int(vv.z));
        g_edges[p3] = make_int2(cc.w, __float_as_int(vv.w));
    } else {
        for (int e = base; e < n_edges; e++) {
            int p = atomicAdd(&g_pos[erow[e]], 1);
            g_edges[p] = make_int2(ecol[e], __float_as_int(evals[e]));
        }
    }
}

// ===========================================================================
// FUSED aggregate + tensor-core GEMM.
// Per 128-row tile: 16 warps each aggregate 8 rows (depth-4 prefetch gather),
// split fp32->bf16 hi/lo in registers, write straight to A smem; then the
// 3-term bf16 split MMA as before. No g_agg round trip.
// ===========================================================================
#define P 136
#define TILE_BYTES (128 * P * 2)
#define SMEM_AHI 0
#define SMEM_ALO (TILE_BYTES)
#define SMEM_BHI (2 * TILE_BYTES)
#define SMEM_BLO (3 * TILE_BYTES)
#define SMEM_TOTAL (4 * TILE_BYTES)

__device__ __forceinline__ uint32_t smem_u32(const void* p) {
    uint32_t a;
    asm("{ .reg .u64 t; cvta.to.shared.u64 t, %1; cvt.u32.u64 %0, t; }"
        : "=r"(a) : "l"(p));
    return a;
}

__device__ __forceinline__ void ldsm_x4(uint32_t addr, uint32_t& r0, uint32_t& r1,
                                        uint32_t& r2, uint32_t& r3) {
    asm volatile("ldmatrix.sync.aligned.m8n8.x4.shared.b16 {%0,%1,%2,%3}, [%4];"
                 : "=r"(r0), "=r"(r1), "=r"(r2), "=r"(r3) : "r"(addr));
}

__device__ __forceinline__ void mma_bf16(float& d0, float& d1, float& d2, float& d3,
                                         uint32_t a0, uint32_t a1, uint32_t a2, uint32_t a3,
                                         uint32_t b0, uint32_t b1) {
    asm volatile("mma.sync.aligned.m16n8k16.row.col.f32.bf16.bf16.f32 "
                 "{%0,%1,%2,%3}, {%4,%5,%6,%7}, {%8,%9}, {%0,%1,%2,%3};"
                 : "+f"(d0), "+f"(d1), "+f"(d2), "+f"(d3)
                 : "r"(a0), "r"(a1), "r"(a2), "r"(a3), "r"(b0), "r"(b1));
}

__device__ __forceinline__ void split2(float a, float b, uint32_t& h, uint32_t& l) {
    __nv_bfloat16 ha = __float2bfloat16(a);
    __nv_bfloat16 hb = __float2bfloat16(b);
    __nv_bfloat16 la = __float2bfloat16(a - __bfloat162float(ha));
    __nv_bfloat16 lb = __float2bfloat16(b - __bfloat162float(hb));
    h = (uint32_t)__bfloat16_as_ushort(ha) | ((uint32_t)__bfloat16_as_ushort(hb) << 16);
    l = (uint32_t)__bfloat16_as_ushort(la) | ((uint32_t)__bfloat16_as_ushort(lb) << 16);
}

__global__ void __launch_bounds__(512, 1)
fused_kernel(const float* __restrict__ x, float* __restrict__ C, int n) {
    extern __shared__ char smem[];
    uint32_t sbase = smem_u32(smem);

    int tid  = threadIdx.x;
    int lane = tid & 31;
    int wid  = tid >> 5;
    int row0 = blockIdx.x << 7;

    // ---- Stage B (hi+lo), 512 threads ----
    {
        const uint4* sh = reinterpret_cast<const uint4*>(g_Whi);
        const uint4* sl = reinterpret_cast<const uint4*>(g_Wlo);
        #pragma unroll
        for (int i = 0; i < 4; i++) {
            int idx = tid + i * 512;           // 2048 uint4 per image
            int r = idx >> 4, c = idx & 15;
            int off = r * (P * 2) + c * 16;
            *reinterpret_cast<uint4*>(smem + SMEM_BHI + off) = sh[idx];
            *reinterpret_cast<uint4*>(smem + SMEM_BLO + off) = sl[idx];
        }
    }

    // ---- Aggregate 8 rows per warp directly into A smem (bf16 hi/lo) ----
    {
        const float4* x4 = reinterpret_cast<const float4*>(x);
        #pragma unroll 1
        for (int r8 = 0; r8 < 8; r8++) {
            int row  = wid * 8 + r8;           // 0..127
            int node = row0 + row;
            float4 acc = make_float4(0.f, 0.f, 0.f, 0.f);
            if (node < n) {
                int beg = g_off[node];
                int end = g_off[node + 1];
                int2 pf[4];
                #pragma unroll
                for (int j = 0; j < 4; j++)
                    pf[j] = (beg + j < end) ? __ldg(&g_edges[beg + j]) : make_int2(0, 0);
                for (int p = beg; p < end; p += 4) {
                    int2 cur[4];
                    #pragma unroll
                    for (int j = 0; j < 4; j++) cur[j] = pf[j];
                    #pragma unroll
                    for (int j = 0; j < 4; j++)
                        pf[j] = (p + 4 + j < end) ? __ldg(&g_edges[p + 4 + j])
                                                  : make_int2(0, 0);
                    #pragma unroll
                    for (int j = 0; j < 4; j++) {
                        if (p + j < end) {
                            float v = __int_as_float(cur[j].y);
                            float4 g = x4[(size_t)cur[j].x * 32 + lane];
                            acc.x = fmaf(v, g.x, acc.x);
                            acc.y = fmaf(v, g.y, acc.y);
                            acc.z = fmaf(v, g.z, acc.z);
                            acc.w = fmaf(v, g.w, acc.w);
                        }
                    }
                }
            }
            uint32_t h0, l0, h1, l1;
            split2(acc.x, acc.y, h0, l0);
            split2(acc.z, acc.w, h1, l1);
            int off = row * (P * 2) + lane * 8;
            *reinterpret_cast<uint2*>(smem + SMEM_AHI + off) = make_uint2(h0, h1);
            *reinterpret_cast<uint2*>(smem + SMEM_ALO + off) = make_uint2(l0, l1);
        }
    }
    __syncthreads();

    // ---- Warp tiling: 4 (M) x 4 (N); warp -> 32x32 output ----
    int wm = wid >> 2;
    int wn = wid & 3;

    int loffA = (lane & 15) * P + (lane >> 4) * 8;
    int loffB = ((lane & 7) + ((lane >> 4) & 1) * 8) * P + ((lane >> 3) & 1) * 8;

    uint32_t aHi = sbase + SMEM_AHI + 2 * (loffA + wm * 32 * P);
    uint32_t aLo = sbase + SMEM_ALO + 2 * (loffA + wm * 32 * P);
    uint32_t bHi = sbase + SMEM_BHI + 2 * (loffB + wn * 32 * P);
    uint32_t bLo = sbase + SMEM_BLO + 2 * (loffB + wn * 32 * P);

    float acc[2][4][4];
    #pragma unroll
    for (int i = 0; i < 2; i++)
        #pragma unroll
        for (int j = 0; j < 4; j++)
            #pragma unroll
            for (int q = 0; q < 4; q++) acc[i][j][q] = 0.f;

    #pragma unroll
    for (int ks = 0; ks < 8; ks++) {
        uint32_t ah[2][4], al[2][4];
        #pragma unroll
        for (int mt = 0; mt < 2; mt++) {
            uint32_t off = (uint32_t)(mt * 16 * P * 2 + ks * 32);
            ldsm_x4(aHi + off, ah[mt][0], ah[mt][1], ah[mt][2], ah[mt][3]);
            ldsm_x4(aLo + off, al[mt][0], al[mt][1], al[mt][2], al[mt][3]);
        }
        uint32_t bh[4][2], bl[4][2];
        #pragma unroll
        for (int nt2 = 0; nt2 < 2; nt2++) {
            uint32_t off = (uint32_t)(nt2 * 16 * P * 2 + ks * 32);
            ldsm_x4(bHi + off, bh[nt2 * 2][0], bh[nt2 * 2][1],
                               bh[nt2 * 2 + 1][0], bh[nt2 * 2 + 1][1]);
            ldsm_x4(bLo + off, bl[nt2 * 2][0], bl[nt2 * 2][1],
                               bl[nt2 * 2 + 1][0], bl[nt2 * 2 + 1][1]);
        }
        #pragma unroll
        for (int mt = 0; mt < 2; mt++)
            #pragma unroll
            for (int nt = 0; nt < 4; nt++) {
                float* d = acc[mt][nt];
                mma_bf16(d[0], d[1], d[2], d[3],
                         ah[mt][0], ah[mt][1], ah[mt][2], ah[mt][3],
                         bh[nt][0], bh[nt][1]);
                mma_bf16(d[0], d[1], d[2], d[3],
                         ah[mt][0], ah[mt][1], ah[mt][2], ah[mt][3],
                         bl[nt][0], bl[nt][1]);
                mma_bf16(d[0], d[1], d[2], d[3],
                         al[mt][0], al[mt][1], al[mt][2], al[mt][3],
                         bh[nt][0], bh[nt][1]);
            }
    }

    int tr = lane >> 2;
    int tc = (lane & 3) * 2;
    #pragma unroll
    for (int mt = 0; mt < 2; mt++) {
        int r_a = row0 + wm * 32 + mt * 16 + tr;
        int r_b = r_a + 8;
        #pragma unroll
        for (int nt = 0; nt < 4; nt++) {
            int col = wn * 32 + nt * 8 + tc;
            if (r_a < n)
                *reinterpret_cast<float2*>(C + (size_t)r_a * D + col) =
                    make_float2(acc[mt][nt][0], acc[mt][nt][1]);
            if (r_b < n)
                *reinterpret_cast<float2*>(C + (size_t)r_b * D + col) =
                    make_float2(acc[mt][nt][2], acc[mt][nt][3]);
        }
    }
}

// ===========================================================================
// Launch
// ===========================================================================
extern "C" void kernel_launch(void* const* d_in, const int* in_sizes, int n_in,
                              void* d_out, int out_size) {
    const float* x     = (const float*)d_in[0];
    const int*   erow  = (const int*)  d_in[1];
    const int*   ecol  = (const int*)  d_in[2];
    const float* evals = (const float*)d_in[3];
    const float* W     = (const float*)d_in[4];
    float*       out   = (float*)d_out;

    int n_nodes = in_sizes[0] / D;   // 100000
    int n_edges = in_sizes[1];       // 1600000

    int scan_blocks = (n_nodes + 1023) / 1024;   // 98 <= 128

    // 1) zero degrees + W prep (merged)
    prep_kernel<<<192, 256>>>(W, n_nodes);
    // 2) histogram
    {
        int nthread = (n_edges + 3) / 4;
        hist_kernel<<<(nthread + 255) / 256, 256>>>(erow, n_edges);
    }
    // 3) scan
    scanA_kernel<<<scan_blocks, 1024>>>(n_nodes);
    scanC_kernel<<<scan_blocks, 1024>>>(scan_blocks, n_nodes);
    // 4) bin
    {
        int nthread = (n_edges + 3) / 4;
        bin_kernel<<<(nthread + 255) / 256, 256>>>(erow, ecol, evals, n_edges);
    }
    // 5) fused aggregate + GEMM -> out
    {
        cudaFuncSetAttribute(fused_kernel,
                             cudaFuncAttributeMaxDynamicSharedMemorySize, SMEM_TOTAL);
        int blocks = (n_nodes + 127) / 128;
        fused_kernel<<<blocks, 512, SMEM_TOTAL>>>(x, out, n_nodes);
    }
}

// round 14
// speedup vs baseline: 1.1748x; 1.1748x over previous
#include <cuda_runtime.h>
#include <cuda_bf16.h>
#include <cstdint>

#define D 128
#define MAX_NODES 100000
#define MAX_EDGES 1600000

// Scratch (no cudaMalloc allowed).
__device__ float    g_agg[(size_t)MAX_NODES * D];
__device__ ushort   g_Whi[D * D];   // bf16 W^T hi: [n][k]
__device__ ushort   g_Wlo[D * D];   // bf16 W^T lo: [n][k]
__device__ int      g_deg[MAX_NODES];
__device__ int      g_off[MAX_NODES + 1];
__device__ int      g_pos[MAX_NODES];
__device__ int      g_bval[128];
__device__ int      g_bflag[128];
__device__ int2     g_edges[MAX_EDGES];   // {src, __float_as_int(val)}

// ===========================================================================
// Kernel 1 (merged): blocks [0,128) zero degree counters (+ scan flags);
//                    blocks [128,192) do W split+transpose.
// ===========================================================================
__global__ void prep_kernel(const float* __restrict__ W, int n) {
    if (blockIdx.x < 128) {
        if (threadIdx.x == 0) { g_bflag[blockIdx.x] = 0; g_bval[blockIdx.x] = 0; }
        int i = blockIdx.x * blockDim.x + threadIdx.x;
        int stride = 128 * blockDim.x;
        for (; i < n; i += stride) g_deg[i] = 0;
    } else {
        int i = (blockIdx.x - 128) * blockDim.x + threadIdx.x;
        if (i >= D * D) return;
        int k = i >> 7, nn = i & 127;
        float w = W[i];
        __nv_bfloat16 h = __float2bfloat16(w);
        float r = w - __bfloat162float(h);
        __nv_bfloat16 l = __float2bfloat16(r);
        g_Whi[nn * D + k] = __bfloat16_as_ushort(h);
        g_Wlo[nn * D + k] = __bfloat16_as_ushort(l);
    }
}

// ===========================================================================
// Histogram: 4 edges per thread via int4 load (MLP=4 on the atomics).
// ===========================================================================
__global__ void hist_kernel(const int* __restrict__ erow, int n_edges) {
    int t = blockIdx.x * blockDim.x + threadIdx.x;
    int base = t * 4;
    if (base + 3 < n_edges) {
        int4 r = reinterpret_cast<const int4*>(erow)[t];
        atomicAdd(&g_deg[r.x], 1);
        atomicAdd(&g_deg[r.y], 1);
        atomicAdd(&g_deg[r.z], 1);
        atomicAdd(&g_deg[r.w], 1);
    } else {
        for (int e = base; e < n_edges; e++) atomicAdd(&g_deg[erow[e]], 1);
    }
}

// ===========================================================================
// Single-pass scan with parallel lookback. 98 blocks, all co-resident
// (98 < 148 SMs): each block publishes its aggregate (fence + flag), then
// every predecessor aggregate is read in parallel (one flag per thread) and
// shfl-reduced. No serial chain.
// ===========================================================================
__global__ void scan_kernel(int nb, int n) {
    __shared__ int s[1024];
    __shared__ int spre[4];
    int t = threadIdx.x;
    int bid = blockIdx.x;
    int i = bid * 1024 + t;

    int v = (i < n) ? g_deg[i] : 0;
    s[t] = v;
    __syncthreads();
    for (int off = 1; off < 1024; off <<= 1) {
        int u = (t >= off) ? s[t - off] : 0;
        __syncthreads();
        s[t] += u;
        __syncthreads();
    }
    int incl = s[t];               // inclusive local prefix
    int agg  = s[1023];            // block aggregate

    // publish aggregate
    if (t == 0) {
        g_bval[bid] = agg;
        __threadfence();
        atomicExch(&g_bflag[bid], 1);
    }

    // lookback: thread t (< bid) fetches predecessor t's aggregate
    int pre = 0;
    if (t < bid) {
        while (atomicAdd(&g_bflag[t], 0) == 0) {}
        pre = g_bval[t];
    }
    #pragma unroll
    for (int o = 16; o > 0; o >>= 1)
        pre += __shfl_down_sync(0xffffffffu, pre, o);
    if (t < 128 && (t & 31) == 0) spre[t >> 5] = pre;
    if (t < 128 && (t & 31) != 0) {}
    __syncthreads();
    int prefix = spre[0] + spre[1] + spre[2] + spre[3];

    if (i < n) {
        int o = prefix + incl - v;     // global exclusive prefix
        g_off[i] = o;
        g_pos[i] = o;
    }
    if (bid == nb - 1 && t == 0) g_off[n] = prefix + agg;
}

// ===========================================================================
// Bin edges into CSR order; 8 edges per thread (MLP=8 on cursor atomics).
// ===========================================================================
__global__ void bin_kernel(const int*   __restrict__ erow,
                           const int*   __restrict__ ecol,
                           const float* __restrict__ evals,
                           int n_edges) {
    int t = blockIdx.x * blockDim.x + threadIdx.x;
    int base = t * 8;
    if (base + 7 < n_edges) {
        const int4*   r4 = reinterpret_cast<const int4*>(erow);
        const int4*   c4 = reinterpret_cast<const int4*>(ecol);
        const float4* v4 = reinterpret_cast<const float4*>(evals);
        int4   rr0 = r4[t * 2],     rr1 = r4[t * 2 + 1];
        int4   cc0 = c4[t * 2],     cc1 = c4[t * 2 + 1];
        float4 vv0 = v4[t * 2],     vv1 = v4[t * 2 + 1];
        int p0 = atomicAdd(&g_pos[rr0.x], 1);
        int p1 = atomicAdd(&g_pos[rr0.y], 1);
        int p2 = atomicAdd(&g_pos[rr0.z], 1);
        int p3 = atomicAdd(&g_pos[rr0.w], 1);
        int p4 = atomicAdd(&g_pos[rr1.x], 1);
        int p5 = atomicAdd(&g_pos[rr1.y], 1);
        int p6 = atomicAdd(&g_pos[rr1.z], 1);
        int p7 = atomicAdd(&g_pos[rr1.w], 1);
        g_edges[p0] = make_int2(cc0.x, __float_as_int(vv0.x));
        g_edges[p1] = make_int2(cc0.y, __float_as_int(vv0.y));
        g_edges[p2] = make_int2(cc0.z, __float_as_int(vv0.z));
        g_edges[p3] = make_int2(cc0.w, __float_as_int(vv0.w));
        g_edges[p4] = make_int2(cc1.x, __float_as_int(vv1.x));
        g_edges[p5] = make_int2(cc1.y, __float_as_int(vv1.y));
        g_edges[p6] = make_int2(cc1.z, __float_as_int(vv1.z));
        g_edges[p7] = make_int2(cc1.w, __float_as_int(vv1.w));
    } else {
        for (int e = base; e < n_edges; e++) {
            int p = atomicAdd(&g_pos[erow[e]], 1);
            g_edges[p] = make_int2(ecol[e], __float_as_int(evals[e]));
        }
    }
}

// ===========================================================================
// Aggregate: warp per dst node, rolling prefetch depth 4 (R11-proven; at the
// L2 gather floor).
// ===========================================================================
__global__ void agg_kernel(const float* __restrict__ x, int n_nodes) {
    int warp = (blockIdx.x * blockDim.x + threadIdx.x) >> 5;
    if (warp >= n_nodes) return;
    int lane = threadIdx.x & 31;

    int beg = g_off[warp];
    int end = g_off[warp + 1];

    const float4* x4 = reinterpret_cast<const float4*>(x);
    float4 acc = make_float4(0.f, 0.f, 0.f, 0.f);

    int2 pf[4];
    #pragma unroll
    for (int j = 0; j < 4; j++)
        pf[j] = (beg + j < end) ? __ldg(&g_edges[beg + j]) : make_int2(0, 0);

    for (int p = beg; p < end; p += 4) {
        int2 cur[4];
        #pragma unroll
        for (int j = 0; j < 4; j++) cur[j] = pf[j];
        #pragma unroll
        for (int j = 0; j < 4; j++)
            pf[j] = (p + 4 + j < end) ? __ldg(&g_edges[p + 4 + j]) : make_int2(0, 0);
        #pragma unroll
        for (int j = 0; j < 4; j++) {
            if (p + j < end) {
                float v = __int_as_float(cur[j].y);
                float4 g = x4[(size_t)cur[j].x * 32 + lane];
                acc.x = fmaf(v, g.x, acc.x);
                acc.y = fmaf(v, g.y, acc.y);
                acc.z = fmaf(v, g.z, acc.z);
                acc.w = fmaf(v, g.w, acc.w);
            }
        }
    }

    reinterpret_cast<float4*>(g_agg)[(size_t)warp * 32 + lane] = acc;
}

// ===========================================================================
// Tensor-core GEMM via mma.sync m16n8k16 bf16 (split, 3 terms).
// M=64 tiles, 256 threads / 8 warps (2M x 4N, warp = 32x32), smem 104.4KB
// -> 2 CTAs/SM for latency hiding.
// ===========================================================================
#define P 136
#define A_TILE_BYTES (64 * P * 2)                // 17408
#define B_TILE_BYTES (128 * P * 2)               // 34816
#define SMEM_AHI 0
#define SMEM_ALO (A_TILE_BYTES)
#define SMEM_BHI (2 * A_TILE_BYTES)
#define SMEM_BLO (2 * A_TILE_BYTES + B_TILE_BYTES)
#define SMEM_TOTAL (2 * A_TILE_BYTES + 2 * B_TILE_BYTES)   // 104448

__device__ __forceinline__ uint32_t smem_u32(const void* p) {
    uint32_t a;
    asm("{ .reg .u64 t; cvta.to.shared.u64 t, %1; cvt.u32.u64 %0, t; }"
        : "=r"(a) : "l"(p));
    return a;
}

__device__ __forceinline__ void ldsm_x4(uint32_t addr, uint32_t& r0, uint32_t& r1,
                                        uint32_t& r2, uint32_t& r3) {
    asm volatile("ldmatrix.sync.aligned.m8n8.x4.shared.b16 {%0,%1,%2,%3}, [%4];"
                 : "=r"(r0), "=r"(r1), "=r"(r2), "=r"(r3) : "r"(addr));
}

__device__ __forceinline__ void mma_bf16(float& d0, float& d1, float& d2, float& d3,
                                         uint32_t a0, uint32_t a1, uint32_t a2, uint32_t a3,
                                         uint32_t b0, uint32_t b1) {
    asm volatile("mma.sync.aligned.m16n8k16.row.col.f32.bf16.bf16.f32 "
                 "{%0,%1,%2,%3}, {%4,%5,%6,%7}, {%8,%9}, {%0,%1,%2,%3};"
                 : "+f"(d0), "+f"(d1), "+f"(d2), "+f"(d3)
                 : "r"(a0), "r"(a1), "r"(a2), "r"(a3), "r"(b0), "r"(b1));
}

__device__ __forceinline__ void split2(float a, float b, uint32_t& h, uint32_t& l) {
    __nv_bfloat16 ha = __float2bfloat16(a);
    __nv_bfloat16 hb = __float2bfloat16(b);
    __nv_bfloat16 la = __float2bfloat16(a - __bfloat162float(ha));
    __nv_bfloat16 lb = __float2bfloat16(b - __bfloat162float(hb));
    h = (uint32_t)__bfloat16_as_ushort(ha) | ((uint32_t)__bfloat16_as_ushort(hb) << 16);
    l = (uint32_t)__bfloat16_as_ushort(la) | ((uint32_t)__bfloat16_as_ushort(lb) << 16);
}

__global__ void __launch_bounds__(256, 2)
gemm_mma_kernel(float* __restrict__ C, int n) {
    extern __shared__ char smem[];
    uint32_t sbase = smem_u32(smem);

    int tid  = threadIdx.x;
    int lane = tid & 31;
    int wid  = tid >> 5;
    int row0 = blockIdx.x << 6;       // 64-row tile

    // ---- Stage B (hi+lo) ----
    {
        const uint4* sh = reinterpret_cast<const uint4*>(g_Whi);
        const uint4* sl = reinterpret_cast<const uint4*>(g_Wlo);
        #pragma unroll
        for (int i = 0; i < 8; i++) {
            int idx = tid + i * 256;          // 2048 uint4 per image
            int r = idx >> 4, c = idx & 15;
            int off = r * (P * 2) + c * 16;
            *reinterpret_cast<uint4*>(smem + SMEM_BHI + off) = sh[idx];
            *reinterpret_cast<uint4*>(smem + SMEM_BLO + off) = sl[idx];
        }
    }
    // ---- Load + split A tile (64 rows) ----
    {
        const float4* ag = reinterpret_cast<const float4*>(g_agg);
        #pragma unroll
        for (int i = 0; i < 8; i++) {
            int idx = tid + i * 256;          // 2048 float4
            int r = idx >> 5, c4 = idx & 31;
            float4 v = make_float4(0.f, 0.f, 0.f, 0.f);
            if (row0 + r < n) v = ag[(size_t)(row0 + r) * 32 + c4];
            uint32_t h0, l0, h1, l1;
            split2(v.x, v.y, h0, l0);
            split2(v.z, v.w, h1, l1);
            int off = r * (P * 2) + c4 * 8;
            *reinterpret_cast<uint2*>(smem + SMEM_AHI + off) = make_uint2(h0, h1);
            *reinterpret_cast<uint2*>(smem + SMEM_ALO + off) = make_uint2(l0, l1);
        }
    }
    __syncthreads();

    // ---- Warp tiling: 2 (M) x 4 (N); warp -> 32x32 output ----
    int wm = wid >> 2;            // 0..1
    int wn = wid & 3;             // 0..3

    int loffA = (lane & 15) * P + (lane >> 4) * 8;
    int loffB = ((lane & 7) + ((lane >> 4) & 1) * 8) * P + ((lane >> 3) & 1) * 8;

    uint32_t aHi = sbase + SMEM_AHI + 2 * (loffA + wm * 32 * P);
    uint32_t aLo = sbase + SMEM_ALO + 2 * (loffA + wm * 32 * P);
    uint32_t bHi = sbase + SMEM_BHI + 2 * (loffB + wn * 32 * P);
    uint32_t bLo = sbase + SMEM_BLO + 2 * (loffB + wn * 32 * P);

    float acc[2][4][4];
    #pragma unroll
    for (int i = 0; i < 2; i++)
        #pragma unroll
        for (int j = 0; j < 4; j++)
            #pragma unroll
            for (int q = 0; q < 4; q++) acc[i][j][q] = 0.f;

    #pragma unroll
    for (int ks = 0; ks < 8; ks++) {
        uint32_t ah[2][4], al[2][4];
        #pragma unroll
        for (int mt = 0; mt < 2; mt++) {
            uint32_t off = (uint32_t)(mt * 16 * P * 2 + ks * 32);
            ldsm_x4(aHi + off, ah[mt][0], ah[mt][1], ah[mt][2], ah[mt][3]);
            ldsm_x4(aLo + off, al[mt][0], al[mt][1], al[mt][2], al[mt][3]);
        }
        uint32_t bh[4][2], bl[4][2];
        #pragma unroll
        for (int nt2 = 0; nt2 < 2; nt2++) {
            uint32_t off = (uint32_t)(nt2 * 16 * P * 2 + ks * 32);
            ldsm_x4(bHi + off, bh[nt2 * 2][0], bh[nt2 * 2][1],
                               bh[nt2 * 2 + 1][0], bh[nt2 * 2 + 1][1]);
            ldsm_x4(bLo + off, bl[nt2 * 2][0], bl[nt2 * 2][1],
                               bl[nt2 * 2 + 1][0], bl[nt2 * 2 + 1][1]);
        }
        #pragma unroll
        for (int mt = 0; mt < 2; mt++)
            #pragma unroll
            for (int nt = 0; nt < 4; nt++) {
                float* d = acc[mt][nt];
                mma_bf16(d[0], d[1], d[2], d[3],
                         ah[mt][0], ah[mt][1], ah[mt][2], ah[mt][3],
                         bh[nt][0], bh[nt][1]);
                mma_bf16(d[0], d[1], d[2], d[3],
                         ah[mt][0], ah[mt][1], ah[mt][2], ah[mt][3],
                         bl[nt][0], bl[nt][1]);
                mma_bf16(d[0], d[1], d[2], d[3],
                         al[mt][0], al[mt][1], al[mt][2], al[mt][3],
                         bh[nt][0], bh[nt][1]);
            }
    }

    int tr = lane >> 2;
    int tc = (lane & 3) * 2;
    #pragma unroll
    for (int mt = 0; mt < 2; mt++) {
        int r_a = row0 + wm * 32 + mt * 16 + tr;
        int r_b = r_a + 8;
        #pragma unroll
        for (int nt = 0; nt < 4; nt++) {
            int col = wn * 32 + nt * 8 + tc;
            if (r_a < n)
                *reinterpret_cast<float2*>(C + (size_t)r_a * D + col) =
                    make_float2(acc[mt][nt][0], acc[mt][nt][1]);
            if (r_b < n)
                *reinterpret_cast<float2*>(C + (size_t)r_b * D + col) =
                    make_float2(acc[mt][nt][2], acc[mt][nt][3]);
        }
    }
}

// ===========================================================================
// Launch
// ===========================================================================
extern "C" void kernel_launch(void* const* d_in, const int* in_sizes, int n_in,
                              void* d_out, int out_size) {
    const float* x     = (const float*)d_in[0];
    const int*   erow  = (const int*)  d_in[1];
    const int*   ecol  = (const int*)  d_in[2];
    const float* evals = (const float*)d_in[3];
    const float* W     = (const float*)d_in[4];
    float*       out   = (float*)d_out;

    int n_nodes = in_sizes[0] / D;   // 100000
    int n_edges = in_sizes[1];       // 1600000

    int scan_blocks = (n_nodes + 1023) / 1024;   // 98 <= 128

    // 1) zero degrees + scan flags + W prep (merged)
    prep_kernel<<<192, 256>>>(W, n_nodes);
    // 2) histogram
    {
        int nthread = (n_edges + 3) / 4;
        hist_kernel<<<(nthread + 255) / 256, 256>>>(erow, n_edges);
    }
    // 3) single-pass scan (parallel lookback)
    scan_kernel<<<scan_blocks, 1024>>>(scan_blocks, n_nodes);
    // 4) bin (8 edges per thread)
    {
        int nthread = (n_edges + 7) / 8;
        bin_kernel<<<(nthread + 255) / 256, 256>>>(erow, ecol, evals, n_edges);
    }
    // 5) aggregate
    agg_kernel<<<(n_nodes + 7) / 8, 256>>>(x, n_nodes);
    // 6) tensor-core GEMM agg @ W -> out (M=64 tiles, 2 CTAs/SM)
    {
        cudaFuncSetAttribute(gemm_mma_kernel,
                             cudaFuncAttributeMaxDynamicSharedMemorySize, SMEM_TOTAL);
        int blocks = (n_nodes + 63) / 64;
        gemm_mma_kernel<<<blocks, 256, SMEM_TOTAL>>>(out, n_nodes);
    }
}

// round 15
// speedup vs baseline: 1.1878x; 1.0110x over previous
#include <cuda_runtime.h>
#include <cuda_bf16.h>
#include <cuda_fp16.h>
#include <cstdint>

#define D 128
#define MAX_NODES 100000
#define MAX_EDGES 1600000

// Scratch (no cudaMalloc allowed).
__device__ float    g_agg[(size_t)MAX_NODES * D];
__device__ uint2    g_xh[(size_t)MAX_NODES * 32];   // fp16 image of x: row = 32 uint2 (4 halfs each)
__device__ ushort   g_Whi[D * D];   // bf16 W^T hi: [n][k]
__device__ ushort   g_Wlo[D * D];   // bf16 W^T lo: [n][k]
__device__ int      g_deg[MAX_NODES];
__device__ int      g_off[MAX_NODES + 1];
__device__ int      g_pos[MAX_NODES];
__device__ int      g_bval[128];
__device__ int      g_bflag[128];
__device__ int2     g_edges[MAX_EDGES];   // {src, __float_as_int(val)}

// ===========================================================================
// Kernel 1 (merged): blocks [0,128): zero degree counters + scan flags;
//                    blocks [128,192): W split+transpose;
//                    blocks [192, ...): convert x -> fp16 image.
// ===========================================================================
__global__ void prep_kernel(const float* __restrict__ W,
                            const float* __restrict__ x, int n) {
    int bid = blockIdx.x;
    if (bid < 128) {
        if (threadIdx.x == 0) { g_bflag[bid] = 0; g_bval[bid] = 0; }
        int i = bid * blockDim.x + threadIdx.x;
        int stride = 128 * blockDim.x;
        for (; i < n; i += stride) g_deg[i] = 0;
    } else if (bid < 192) {
        int i = (bid - 128) * blockDim.x + threadIdx.x;
        if (i >= D * D) return;
        int k = i >> 7, nn = i & 127;
        float w = W[i];
        __nv_bfloat16 h = __float2bfloat16(w);
        float r = w - __bfloat162float(h);
        __nv_bfloat16 l = __float2bfloat16(r);
        g_Whi[nn * D + k] = __bfloat16_as_ushort(h);
        g_Wlo[nn * D + k] = __bfloat16_as_ushort(l);
    } else {
        // x -> fp16: each thread converts one float4 -> one uint2 (4 halfs)
        int i = (bid - 192) * blockDim.x + threadIdx.x;
        int total = n * 32;                    // 32 float4 per row
        if (i < total) {
            float4 v = reinterpret_cast<const float4*>(x)[i];
            half2 h0 = __floats2half2_rn(v.x, v.y);
            half2 h1 = __floats2half2_rn(v.z, v.w);
            uint2 o;
            o.x = *reinterpret_cast<uint32_t*>(&h0);
            o.y = *reinterpret_cast<uint32_t*>(&h1);
            g_xh[i] = o;
        }
    }
}

// ===========================================================================
// Histogram: 4 edges per thread via int4 load (MLP=4 on the atomics).
// ===========================================================================
__global__ void hist_kernel(const int* __restrict__ erow, int n_edges) {
    int t = blockIdx.x * blockDim.x + threadIdx.x;
    int base = t * 4;
    if (base + 3 < n_edges) {
        int4 r = reinterpret_cast<const int4*>(erow)[t];
        atomicAdd(&g_deg[r.x], 1);
        atomicAdd(&g_deg[r.y], 1);
        atomicAdd(&g_deg[r.z], 1);
        atomicAdd(&g_deg[r.w], 1);
    } else {
        for (int e = base; e < n_edges; e++) atomicAdd(&g_deg[erow[e]], 1);
    }
}

// ===========================================================================
// Single-pass scan with parallel lookback (98 co-resident blocks).
// ===========================================================================
__global__ void scan_kernel(int nb, int n) {
    __shared__ int s[1024];
    __shared__ int spre[4];
    int t = threadIdx.x;
    int bid = blockIdx.x;
    int i = bid * 1024 + t;

    int v = (i < n) ? g_deg[i] : 0;
    s[t] = v;
    __syncthreads();
    for (int off = 1; off < 1024; off <<= 1) {
        int u = (t >= off) ? s[t - off] : 0;
        __syncthreads();
        s[t] += u;
        __syncthreads();
    }
    int incl = s[t];
    int agg  = s[1023];

    if (t == 0) {
        g_bval[bid] = agg;
        __threadfence();
        atomicExch(&g_bflag[bid], 1);
    }

    int pre = 0;
    if (t < bid) {
        while (atomicAdd(&g_bflag[t], 0) == 0) {}
        pre = g_bval[t];
    }
    #pragma unroll
    for (int o = 16; o > 0; o >>= 1)
        pre += __shfl_down_sync(0xffffffffu, pre, o);
    if (t < 128 && (t & 31) == 0) spre[t >> 5] = pre;
    __syncthreads();
    int prefix = spre[0] + spre[1] + spre[2] + spre[3];

    if (i < n) {
        int o = prefix + incl - v;
        g_off[i] = o;
        g_pos[i] = o;
    }
    if (bid == nb - 1 && t == 0) g_off[n] = prefix + agg;
}

// ===========================================================================
// Bin edges into CSR order; 4 edges per thread (reverted: best measured).
// ===========================================================================
__global__ void bin_kernel(const int*   __restrict__ erow,
                           const int*   __restrict__ ecol,
                           const float* __restrict__ evals,
                           int n_edges) {
    int t = blockIdx.x * blockDim.x + threadIdx.x;
    int base = t * 4;
    if (base + 3 < n_edges) {
        int4   rr = reinterpret_cast<const int4*>(erow)[t];
        int4   cc = reinterpret_cast<const int4*>(ecol)[t];
        float4 vv = reinterpret_cast<const float4*>(evals)[t];
        int p0 = atomicAdd(&g_pos[rr.x], 1);
        int p1 = atomicAdd(&g_pos[rr.y], 1);
        int p2 = atomicAdd(&g_pos[rr.z], 1);
        int p3 = atomicAdd(&g_pos[rr.w], 1);
        g_edges[p0] = make_int2(cc.x, __float_as_int(vv.x));
        g_edges[p1] = make_int2(cc.y, __float_as_int(vv.y));
        g_edges[p2] = make_int2(cc.z, __float_as_int(vv.z));
        g_edges[p3] = make_int2(cc.w, __float_as_int(vv.w));
    } else {
        for (int e = base; e < n_edges; e++) {
            int p = atomicAdd(&g_pos[erow[e]], 1);
            g_edges[p] = make_int2(ecol[e], __float_as_int(evals[e]));
        }
    }
}

// ===========================================================================
// Aggregate: warp per dst node, depth-4 prefetch; gathers the fp16 image
// (8B/lane instead of 16B -> half the L2 gather traffic). fp32 accumulate.
// ===========================================================================
__global__ void agg_kernel(int n_nodes) {
    int warp = (blockIdx.x * blockDim.x + threadIdx.x) >> 5;
    if (warp >= n_nodes) return;
    int lane = threadIdx.x & 31;

    int beg = g_off[warp];
    int end = g_off[warp + 1];

    float4 acc = make_float4(0.f, 0.f, 0.f, 0.f);

    int2 pf[4];
    #pragma unroll
    for (int j = 0; j < 4; j++)
        pf[j] = (beg + j < end) ? __ldg(&g_edges[beg + j]) : make_int2(0, 0);

    for (int p = beg; p < end; p += 4) {
        int2 cur[4];
        #pragma unroll
        for (int j = 0; j < 4; j++) cur[j] = pf[j];
        #pragma unroll
        for (int j = 0; j < 4; j++)
            pf[j] = (p + 4 + j < end) ? __ldg(&g_edges[p + 4 + j]) : make_int2(0, 0);
        #pragma unroll
        for (int j = 0; j < 4; j++) {
            if (p + j < end) {
                float v = __int_as_float(cur[j].y);
                uint2 raw = __ldg(&g_xh[(size_t)cur[j].x * 32 + lane]);
                half2 h0 = *reinterpret_cast<half2*>(&raw.x);
                half2 h1 = *reinterpret_cast<half2*>(&raw.y);
                float2 f0 = __half22float2(h0);
                float2 f1 = __half22float2(h1);
                acc.x = fmaf(v, f0.x, acc.x);
                acc.y = fmaf(v, f0.y, acc.y);
                acc.z = fmaf(v, f1.x, acc.z);
                acc.w = fmaf(v, f1.y, acc.w);
            }
        }
    }

    reinterpret_cast<float4*>(g_agg)[(size_t)warp * 32 + lane] = acc;
}

// ===========================================================================
// Tensor-core GEMM via mma.sync m16n8k16 bf16 (split, 3 terms).
// M=64 tiles, 256 threads / 8 warps, 2 CTAs/SM (unchanged from R14).
// ===========================================================================
#define P 136
#define A_TILE_BYTES (64 * P * 2)
#define B_TILE_BYTES (128 * P * 2)
#define SMEM_AHI 0
#define SMEM_ALO (A_TILE_BYTES)
#define SMEM_BHI (2 * A_TILE_BYTES)
#define SMEM_BLO (2 * A_TILE_BYTES + B_TILE_BYTES)
#define SMEM_TOTAL (2 * A_TILE_BYTES + 2 * B_TILE_BYTES)   // 104448

__device__ __forceinline__ uint32_t smem_u32(const void* p) {
    uint32_t a;
    asm("{ .reg .u64 t; cvta.to.shared.u64 t, %1; cvt.u32.u64 %0, t; }"
        : "=r"(a) : "l"(p));
    return a;
}

__device__ __forceinline__ void ldsm_x4(uint32_t addr, uint32_t& r0, uint32_t& r1,
                                        uint32_t& r2, uint32_t& r3) {
    asm volatile("ldmatrix.sync.aligned.m8n8.x4.shared.b16 {%0,%1,%2,%3}, [%4];"
                 : "=r"(r0), "=r"(r1), "=r"(r2), "=r"(r3) : "r"(addr));
}

__device__ __forceinline__ void mma_bf16(float& d0, float& d1, float& d2, float& d3,
                                         uint32_t a0, uint32_t a1, uint32_t a2, uint32_t a3,
                                         uint32_t b0, uint32_t b1) {
    asm volatile("mma.sync.aligned.m16n8k16.row.col.f32.bf16.bf16.f32 "
                 "{%0,%1,%2,%3}, {%4,%5,%6,%7}, {%8,%9}, {%0,%1,%2,%3};"
                 : "+f"(d0), "+f"(d1), "+f"(d2), "+f"(d3)
                 : "r"(a0), "r"(a1), "r"(a2), "r"(a3), "r"(b0), "r"(b1));
}

__device__ __forceinline__ void split2(float a, float b, uint32_t& h, uint32_t& l) {
    __nv_bfloat16 ha = __float2bfloat16(a);
    __nv_bfloat16 hb = __float2bfloat16(b);
    __nv_bfloat16 la = __float2bfloat16(a - __bfloat162float(ha));
    __nv_bfloat16 lb = __float2bfloat16(b - __bfloat162float(hb));
    h = (uint32_t)__bfloat16_as_ushort(ha) | ((uint32_t)__bfloat16_as_ushort(hb) << 16);
    l = (uint32_t)__bfloat16_as_ushort(la) | ((uint32_t)__bfloat16_as_ushort(lb) << 16);
}

__global__ void __launch_bounds__(256, 2)
gemm_mma_kernel(float* __restrict__ C, int n) {
    extern __shared__ char smem[];
    uint32_t sbase = smem_u32(smem);

    int tid  = threadIdx.x;
    int lane = tid & 31;
    int wid  = tid >> 5;
    int row0 = blockIdx.x << 6;

    {
        const uint4* sh = reinterpret_cast<const uint4*>(g_Whi);
        const uint4* sl = reinterpret_cast<const uint4*>(g_Wlo);
        #pragma unroll
        for (int i = 0; i < 8; i++) {
            int idx = tid + i * 256;
            int r = idx >> 4, c = idx & 15;
            int off = r * (P * 2) + c * 16;
            *reinterpret_cast<uint4*>(smem + SMEM_BHI + off) = sh[idx];
            *reinterpret_cast<uint4*>(smem + SMEM_BLO + off) = sl[idx];
        }
    }
    {
        const float4* ag = reinterpret_cast<const float4*>(g_agg);
        #pragma unroll
        for (int i = 0; i < 8; i++) {
            int idx = tid + i * 256;
            int r = idx >> 5, c4 = idx & 31;
            float4 v = make_float4(0.f, 0.f, 0.f, 0.f);
            if (row0 + r < n) v = ag[(size_t)(row0 + r) * 32 + c4];
            uint32_t h0, l0, h1, l1;
            split2(v.x, v.y, h0, l0);
            split2(v.z, v.w, h1, l1);
            int off = r * (P * 2) + c4 * 8;
            *reinterpret_cast<uint2*>(smem + SMEM_AHI + off) = make_uint2(h0, h1);
            *reinterpret_cast<uint2*>(smem + SMEM_ALO + off) = make_uint2(l0, l1);
        }
    }
    __syncthreads();

    int wm = wid >> 2;
    int wn = wid & 3;

    int loffA = (lane & 15) * P + (lane >> 4) * 8;
    int loffB = ((lane & 7) + ((lane >> 4) & 1) * 8) * P + ((lane >> 3) & 1) * 8;

    uint32_t aHi = sbase + SMEM_AHI + 2 * (loffA + wm * 32 * P);
    uint32_t aLo = sbase + SMEM_ALO + 2 * (loffA + wm * 32 * P);
    uint32_t bHi = sbase + SMEM_BHI + 2 * (loffB + wn * 32 * P);
    uint32_t bLo = sbase + SMEM_BLO + 2 * (loffB + wn * 32 * P);

    float acc[2][4][4];
    #pragma unroll
    for (int i = 0; i < 2; i++)
        #pragma unroll
        for (int j = 0; j < 4; j++)
            #pragma unroll
            for (int q = 0; q < 4; q++) acc[i][j][q] = 0.f;

    #pragma unroll
    for (int ks = 0; ks < 8; ks++) {
        uint32_t ah[2][4], al[2][4];
        #pragma unroll
        for (int mt = 0; mt < 2; mt++) {
            uint32_t off = (uint32_t)(mt * 16 * P * 2 + ks * 32);
            ldsm_x4(aHi + off, ah[mt][0], ah[mt][1], ah[mt][2], ah[mt][3]);
            ldsm_x4(aLo + off, al[mt][0], al[mt][1], al[mt][2], al[mt][3]);
        }
        uint32_t bh[4][2], bl[4][2];
        #pragma unroll
        for (int nt2 = 0; nt2 < 2; nt2++) {
            uint32_t off = (uint32_t)(nt2 * 16 * P * 2 + ks * 32);
            ldsm_x4(bHi + off, bh[nt2 * 2][0], bh[nt2 * 2][1],
                               bh[nt2 * 2 + 1][0], bh[nt2 * 2 + 1][1]);
            ldsm_x4(bLo + off, bl[nt2 * 2][0], bl[nt2 * 2][1],
                               bl[nt2 * 2 + 1][0], bl[nt2 * 2 + 1][1]);
        }
        #pragma unroll
        for (int mt = 0; mt < 2; mt++)
            #pragma unroll
            for (int nt = 0; nt < 4; nt++) {
                float* d = acc[mt][nt];
                mma_bf16(d[0], d[1], d[2], d[3],
                         ah[mt][0], ah[mt][1], ah[mt][2], ah[mt][3],
                         bh[nt][0], bh[nt][1]);
                mma_bf16(d[0], d[1], d[2], d[3],
                         ah[mt][0], ah[mt][1], ah[mt][2], ah[mt][3],
                         bl[nt][0], bl[nt][1]);
                mma_bf16(d[0], d[1], d[2], d[3],
                         al[mt][0], al[mt][1], al[mt][2], al[mt][3],
                         bh[nt][0], bh[nt][1]);
            }
    }

    int tr = lane >> 2;
    int tc = (lane & 3) * 2;
    #pragma unroll
    for (int mt = 0; mt < 2; mt++) {
        int r_a = row0 + wm * 32 + mt * 16 + tr;
        int r_b = r_a + 8;
        #pragma unroll
        for (int nt = 0; nt < 4; nt++) {
            int col = wn * 32 + nt * 8 + tc;
            if (r_a < n)
                *reinterpret_cast<float2*>(C + (size_t)r_a * D + col) =
                    make_float2(acc[mt][nt][0], acc[mt][nt][1]);
            if (r_b < n)
                *reinterpret_cast<float2*>(C + (size_t)r_b * D + col) =
                    make_float2(acc[mt][nt][2], acc[mt][nt][3]);
        }
    }
}

// ===========================================================================
// Launch
// ===========================================================================
extern "C" void kernel_launch(void* const* d_in, const int* in_sizes, int n_in,
                              void* d_out, int out_size) {
    const float* x     = (const float*)d_in[0];
    const int*   erow  = (const int*)  d_in[1];
    const int*   ecol  = (const int*)  d_in[2];
    const float* evals = (const float*)d_in[3];
    const float* W     = (const float*)d_in[4];
    float*       out   = (float*)d_out;

    int n_nodes = in_sizes[0] / D;   // 100000
    int n_edges = in_sizes[1];       // 1600000

    int scan_blocks = (n_nodes + 1023) / 1024;   // 98 <= 128
    int conv_blocks = (n_nodes * 32 + 255) / 256;

    // 1) zero degrees + scan flags + W prep + x->fp16 (merged)
    prep_kernel<<<192 + conv_blocks, 256>>>(W, x, n_nodes);
    // 2) histogram
    {
        int nthread = (n_edges + 3) / 4;
        hist_kernel<<<(nthread + 255) / 256, 256>>>(erow, n_edges);
    }
    // 3) single-pass scan (parallel lookback)
    scan_kernel<<<scan_blocks, 1024>>>(scan_blocks, n_nodes);
    // 4) bin (4 edges per thread — reverted)
    {
        int nthread = (n_edges + 3) / 4;
        bin_kernel<<<(nthread + 255) / 256, 256>>>(erow, ecol, evals, n_edges);
    }
    // 5) aggregate (fp16 gathers)
    agg_kernel<<<(n_nodes + 7) / 8, 256>>>(n_nodes);
    // 6) tensor-core GEMM agg @ W -> out
    {
        cudaFuncSetAttribute(gemm_mma_kernel,
                             cudaFuncAttributeMaxDynamicSharedMemorySize, SMEM_TOTAL);
        int blocks = (n_nodes + 63) / 64;
        gemm_mma_kernel<<<blocks, 256, SMEM_TOTAL>>>(out, n_nodes);
    }
}

// round 17
// speedup vs baseline: 1.3144x; 1.1066x over previous
#include <cuda_runtime.h>
#include <cuda_bf16.h>
#include <cuda_fp16.h>
#include <cstdint>

#define D 128
#define MAX_NODES 100000
#define MAX_EDGES 1600000

// Scratch (no cudaMalloc allowed).
__device__ uint2    g_Y[(size_t)MAX_NODES * 32];    // fp16 image of Y = x@W (row = 32 uint2)
__device__ ushort   g_Whi[D * D];   // bf16 W^T hi: [n][k]
__device__ ushort   g_Wlo[D * D];   // bf16 W^T lo: [n][k]
__device__ int      g_deg[MAX_NODES];
__device__ int      g_off[MAX_NODES + 1];
__device__ int      g_pos[MAX_NODES];
__device__ int      g_bval[128];
__device__ int      g_bflag[128];
__device__ int2     g_edges[MAX_EDGES];   // {src, __float_as_int(val)}

// ===========================================================================
// Kernel 1 (merged): blocks [0,128): zero degree counters + scan flags;
//                    blocks [128,192): W split+transpose.
// ===========================================================================
__global__ void prep_kernel(const float* __restrict__ W, int n) {
    int bid = blockIdx.x;
    if (bid < 128) {
        if (threadIdx.x == 0) { g_bflag[bid] = 0; g_bval[bid] = 0; }
        int i = bid * blockDim.x + threadIdx.x;
        int stride = 128 * blockDim.x;
        for (; i < n; i += stride) g_deg[i] = 0;
    } else {
        int i = (bid - 128) * blockDim.x + threadIdx.x;
        if (i >= D * D) return;
        int k = i >> 7, nn = i & 127;
        float w = W[i];
        __nv_bfloat16 h = __float2bfloat16(w);
        float r = w - __bfloat162float(h);
        __nv_bfloat16 l = __float2bfloat16(r);
        g_Whi[nn * D + k] = __bfloat16_as_ushort(h);
        g_Wlo[nn * D + k] = __bfloat16_as_ushort(l);
    }
}

// ===========================================================================
// Histogram: 4 edges per thread via int4 load.
// ===========================================================================
__global__ void hist_kernel(const int* __restrict__ erow, int n_edges) {
    int t = blockIdx.x * blockDim.x + threadIdx.x;
    int base = t * 4;
    if (base + 3 < n_edges) {
        int4 r = reinterpret_cast<const int4*>(erow)[t];
        atomicAdd(&g_deg[r.x], 1);
        atomicAdd(&g_deg[r.y], 1);
        atomicAdd(&g_deg[r.z], 1);
        atomicAdd(&g_deg[r.w], 1);
    } else {
        for (int e = base; e < n_edges; e++) atomicAdd(&g_deg[erow[e]], 1);
    }
}

// ===========================================================================
// Single-pass scan with parallel lookback (98 co-resident blocks).
// ===========================================================================
__global__ void scan_kernel(int nb, int n) {
    __shared__ int s[1024];
    __shared__ int spre[4];
    int t = threadIdx.x;
    int bid = blockIdx.x;
    int i = bid * 1024 + t;

    int v = (i < n) ? g_deg[i] : 0;
    s[t] = v;
    __syncthreads();
    for (int off = 1; off < 1024; off <<= 1) {
        int u = (t >= off) ? s[t - off] : 0;
        __syncthreads();
        s[t] += u;
        __syncthreads();
    }
    int incl = s[t];
    int agg  = s[1023];

    if (t == 0) {
        g_bval[bid] = agg;
        __threadfence();
        atomicExch(&g_bflag[bid], 1);
    }

    int pre = 0;
    if (t < bid) {
        while (atomicAdd(&g_bflag[t], 0) == 0) {}
        pre = g_bval[t];
    }
    #pragma unroll
    for (int o = 16; o > 0; o >>= 1)
        pre += __shfl_down_sync(0xffffffffu, pre, o);
    if (t < 128 && (t & 31) == 0) spre[t >> 5] = pre;
    __syncthreads();
    int prefix = spre[0] + spre[1] + spre[2] + spre[3];

    if (i < n) {
        int o = prefix + incl - v;
        g_off[i] = o;
        g_pos[i] = o;
    }
    if (bid == nb - 1 && t == 0) g_off[n] = prefix + agg;
}

// ===========================================================================
// Bin edges into CSR order; 4 edges per thread (proven best).
// ===========================================================================
__global__ void bin_kernel(const int*   __restrict__ erow,
                           const int*   __restrict__ ecol,
                           const float* __restrict__ evals,
                           int n_edges) {
    int t = blockIdx.x * blockDim.x + threadIdx.x;
    int base = t * 4;
    if (base + 3 < n_edges) {
        int4   rr = reinterpret_cast<const int4*>(erow)[t];
        int4   cc = reinterpret_cast<const int4*>(ecol)[t];
        float4 vv = reinterpret_cast<const float4*>(evals)[t];
        int p0 = atomicAdd(&g_pos[rr.x], 1);
        int p1 = atomicAdd(&g_pos[rr.y], 1);
        int p2 = atomicAdd(&g_pos[rr.z], 1);
        int p3 = atomicAdd(&g_pos[rr.w], 1);
        g_edges[p0] = make_int2(cc.x, __float_as_int(vv.x));
        g_edges[p1] = make_int2(cc.y, __float_as_int(vv.y));
        g_edges[p2] = make_int2(cc.z, __float_as_int(vv.z));
        g_edges[p3] = make_int2(cc.w, __float_as_int(vv.w));
    } else {
        for (int e = base; e < n_edges; e++) {
            int p = atomicAdd(&g_pos[erow[e]], 1);
            g_edges[p] = make_int2(ecol[e], __float_as_int(evals[e]));
        }
    }
}

// ===========================================================================
// Persistent tensor-core GEMM: Y[n,128] = x[n,128] @ W (fp16 output image).
// bf16 split (3 terms), fp32 accum. M=64 tiles, grid-stride tile loop,
// B staged ONCE per CTA. 256 thr / 8 warps (2M x 4N), 2 CTAs/SM.
// ===========================================================================
#define P 136
#define A_TILE_BYTES (64 * P * 2)
#define B_TILE_BYTES (128 * P * 2)
#define SMEM_AHI 0
#define SMEM_ALO (A_TILE_BYTES)
#define SMEM_BHI (2 * A_TILE_BYTES)
#define SMEM_BLO (2 * A_TILE_BYTES + B_TILE_BYTES)
#define SMEM_TOTAL (2 * A_TILE_BYTES + 2 * B_TILE_BYTES)   // 104448

__device__ __forceinline__ uint32_t smem_u32(const void* p) {
    uint32_t a;
    asm("{ .reg .u64 t; cvta.to.shared.u64 t, %1; cvt.u32.u64 %0, t; }"
        : "=r"(a) : "l"(p));
    return a;
}

__device__ __forceinline__ void ldsm_x4(uint32_t addr, uint32_t& r0, uint32_t& r1,
                                        uint32_t& r2, uint32_t& r3) {
    asm volatile("ldmatrix.sync.aligned.m8n8.x4.shared.b16 {%0,%1,%2,%3}, [%4];"
                 : "=r"(r0), "=r"(r1), "=r"(r2), "=r"(r3) : "r"(addr));
}

__device__ __forceinline__ void mma_bf16(float& d0, float& d1, float& d2, float& d3,
                                         uint32_t a0, uint32_t a1, uint32_t a2, uint32_t a3,
                                         uint32_t b0, uint32_t b1) {
    asm volatile("mma.sync.aligned.m16n8k16.row.col.f32.bf16.bf16.f32 "
                 "{%0,%1,%2,%3}, {%4,%5,%6,%7}, {%8,%9}, {%0,%1,%2,%3};"
                 : "+f"(d0), "+f"(d1), "+f"(d2), "+f"(d3)
                 : "r"(a0), "r"(a1), "r"(a2), "r"(a3), "r"(b0), "r"(b1));
}

__device__ __forceinline__ void split2(float a, float b, uint32_t& h, uint32_t& l) {
    __nv_bfloat16 ha = __float2bfloat16(a);
    __nv_bfloat16 hb = __float2bfloat16(b);
    __nv_bfloat16 la = __float2bfloat16(a - __bfloat162float(ha));
    __nv_bfloat16 lb = __float2bfloat16(b - __bfloat162float(hb));
    h = (uint32_t)__bfloat16_as_ushort(ha) | ((uint32_t)__bfloat16_as_ushort(hb) << 16);
    l = (uint32_t)__bfloat16_as_ushort(la) | ((uint32_t)__bfloat16_as_ushort(lb) << 16);
}

__global__ void __launch_bounds__(256, 2)
gemmY_kernel(const float* __restrict__ x, int n) {
    extern __shared__ char smem[];
    uint32_t sbase = smem_u32(smem);

    int tid  = threadIdx.x;
    int lane = tid & 31;
    int wid  = tid >> 5;

    // ---- Stage B (hi+lo) ONCE ----
    {
        const uint4* sh = reinterpret_cast<const uint4*>(g_Whi);
        const uint4* sl = reinterpret_cast<const uint4*>(g_Wlo);
        #pragma unroll
        for (int i = 0; i < 8; i++) {
            int idx = tid + i * 256;
            int r = idx >> 4, c = idx & 15;
            int off = r * (P * 2) + c * 16;
            *reinterpret_cast<uint4*>(smem + SMEM_BHI + off) = sh[idx];
            *reinterpret_cast<uint4*>(smem + SMEM_BLO + off) = sl[idx];
        }
    }

    int wm = wid >> 2;
    int wn = wid & 3;
    int loffA = (lane & 15) * P + (lane >> 4) * 8;
    int loffB = ((lane & 7) + ((lane >> 4) & 1) * 8) * P + ((lane >> 3) & 1) * 8;
    uint32_t aHi = sbase + SMEM_AHI + 2 * (loffA + wm * 32 * P);
    uint32_t aLo = sbase + SMEM_ALO + 2 * (loffA + wm * 32 * P);
    uint32_t bHi = sbase + SMEM_BHI + 2 * (loffB + wn * 32 * P);
    uint32_t bLo = sbase + SMEM_BLO + 2 * (loffB + wn * 32 * P);

    __half* Yh = reinterpret_cast<__half*>(g_Y);
    int ntiles = (n + 63) >> 6;

    for (int tile = blockIdx.x; tile < ntiles; tile += gridDim.x) {
        int row0 = tile << 6;

        __syncthreads();   // A smem free from previous iteration (also orders B, iter 0)
        {
            const float4* ag = reinterpret_cast<const float4*>(x);
            #pragma unroll
            for (int i = 0; i < 8; i++) {
                int idx = tid + i * 256;          // 2048 float4
                int r = idx >> 5, c4 = idx & 31;
                float4 v = make_float4(0.f, 0.f, 0.f, 0.f);
                if (row0 + r < n) v = ag[(size_t)(row0 + r) * 32 + c4];
                uint32_t h0, l0, h1, l1;
                split2(v.x, v.y, h0, l0);
                split2(v.z, v.w, h1, l1);
                int off = r * (P * 2) + c4 * 8;
                *reinterpret_cast<uint2*>(smem + SMEM_AHI + off) = make_uint2(h0, h1);
                *reinterpret_cast<uint2*>(smem + SMEM_ALO + off) = make_uint2(l0, l1);
            }
        }
        __syncthreads();

        float acc[2][4][4];
        #pragma unroll
        for (int i = 0; i < 2; i++)
            #pragma unroll
            for (int j = 0; j < 4; j++)
                #pragma unroll
                for (int q = 0; q < 4; q++) acc[i][j][q] = 0.f;

        #pragma unroll
        for (int ks = 0; ks < 8; ks++) {
            uint32_t ah[2][4], al[2][4];
            #pragma unroll
            for (int mt = 0; mt < 2; mt++) {
                uint32_t off = (uint32_t)(mt * 16 * P * 2 + ks * 32);
                ldsm_x4(aHi + off, ah[mt][0], ah[mt][1], ah[mt][2], ah[mt][3]);
                ldsm_x4(aLo + off, al[mt][0], al[mt][1], al[mt][2], al[mt][3]);
            }
            uint32_t bh[4][2], bl[4][2];
            #pragma unroll
            for (int nt2 = 0; nt2 < 2; nt2++) {
                uint32_t off = (uint32_t)(nt2 * 16 * P * 2 + ks * 32);
                ldsm_x4(bHi + off, bh[nt2 * 2][0], bh[nt2 * 2][1],
                                   bh[nt2 * 2 + 1][0], bh[nt2 * 2 + 1][1]);
                ldsm_x4(bLo + off, bl[nt2 * 2][0], bl[nt2 * 2][1],
                                   bl[nt2 * 2 + 1][0], bl[nt2 * 2 + 1][1]);
            }
            #pragma unroll
            for (int mt = 0; mt < 2; mt++)
                #pragma unroll
                for (int nt = 0; nt < 4; nt++) {
                    float* d = acc[mt][nt];
                    mma_bf16(d[0], d[1], d[2], d[3],
                             ah[mt][0], ah[mt][1], ah[mt][2], ah[mt][3],
                             bh[nt][0], bh[nt][1]);
                    mma_bf16(d[0], d[1], d[2], d[3],
                             ah[mt][0], ah[mt][1], ah[mt][2], ah[mt][3],
                             bl[nt][0], bl[nt][1]);
                    mma_bf16(d[0], d[1], d[2], d[3],
                             al[mt][0], al[mt][1], al[mt][2], al[mt][3],
                             bh[nt][0], bh[nt][1]);
                }
        }

        // Epilogue: fp16 Y image
        int tr = lane >> 2;
        int tc = (lane & 3) * 2;
        #pragma unroll
        for (int mt = 0; mt < 2; mt++) {
            int r_a = row0 + wm * 32 + mt * 16 + tr;
            int r_b = r_a + 8;
            #pragma unroll
            for (int nt = 0; nt < 4; nt++) {
                int col = wn * 32 + nt * 8 + tc;
                if (r_a < n)
                    *reinterpret_cast<half2*>(Yh + (size_t)r_a * D + col) =
                        __floats2half2_rn(acc[mt][nt][0], acc[mt][nt][1]);
                if (r_b < n)
                    *reinterpret_cast<half2*>(Yh + (size_t)r_b * D + col) =
                        __floats2half2_rn(acc[mt][nt][2], acc[mt][nt][3]);
            }
        }
    }
}

// ===========================================================================
// Aggregate: warp per dst node, depth-4 prefetch, gathers fp16 Y rows,
// fp32 accumulate, writes DIRECTLY to out. (Inner loop = R15-proven.)
// ===========================================================================
__global__ void agg_kernel(float* __restrict__ out, int n_nodes) {
    int warp = (blockIdx.x * blockDim.x + threadIdx.x) >> 5;
    if (warp >= n_nodes) return;
    int lane = threadIdx.x & 31;

    int beg = g_off[warp];
    int end = g_off[warp + 1];

    float4 acc = make_float4(0.f, 0.f, 0.f, 0.f);

    int2 pf[4];
    #pragma unroll
    for (int j = 0; j < 4; j++)
        pf[j] = (beg + j < end) ? __ldg(&g_edges[beg + j]) : make_int2(0, 0);

    for (int p = beg; p < end; p += 4) {
        int2 cur[4];
        #pragma unroll
        for (int j = 0; j < 4; j++) cur[j] = pf[j];
        #pragma unroll
        for (int j = 0; j < 4; j++)
            pf[j] = (p + 4 + j < end) ? __ldg(&g_edges[p + 4 + j]) : make_int2(0, 0);
        #pragma unroll
        for (int j = 0; j < 4; j++) {
            if (p + j < end) {
                float v = __int_as_float(cur[j].y);
                uint2 raw = __ldg(&g_Y[(size_t)cur[j].x * 32 + lane]);
                half2 h0 = *reinterpret_cast<half2*>(&raw.x);
                half2 h1 = *reinterpret_cast<half2*>(&raw.y);
                float2 f0 = __half22float2(h0);
                float2 f1 = __half22float2(h1);
                acc.x = fmaf(v, f0.x, acc.x);
                acc.y = fmaf(v, f0.y, acc.y);
                acc.z = fmaf(v, f1.x, acc.z);
                acc.w = fmaf(v, f1.y, acc.w);
            }
        }
    }

    reinterpret_cast<float4*>(out)[(size_t)warp * 32 + lane] = acc;
}

// ===========================================================================
// Launch
// ===========================================================================
extern "C" void kernel_launch(void* const* d_in, const int* in_sizes, int n_in,
                              void* d_out, int out_size) {
    const float* x     = (const float*)d_in[0];
    const int*   erow  = (const int*)  d_in[1];
    const int*   ecol  = (const int*)  d_in[2];
    const float* evals = (const float*)d_in[3];
    const float* W     = (const float*)d_in[4];
    float*       out   = (float*)d_out;

    int n_nodes = in_sizes[0] / D;   // 100000
    int n_edges = in_sizes[1];       // 1600000

    int scan_blocks = (n_nodes + 1023) / 1024;   // 98 <= 128

    // 1) zero degrees + scan flags + W prep
    prep_kernel<<<192, 256>>>(W, n_nodes);
    // 2) histogram
    {
        int nthread = (n_edges + 3) / 4;
        hist_kernel<<<(nthread + 255) / 256, 256>>>(erow, n_edges);
    }
    // 3) single-pass scan (parallel lookback)
    scan_kernel<<<scan_blocks, 1024>>>(scan_blocks, n_nodes);
    // 4) bin
    {
        int nthread = (n_edges + 3) / 4;
        bin_kernel<<<(nthread + 255) / 256, 256>>>(erow, ecol, evals, n_edges);
    }
    // 5) Y = x @ W (persistent tensor-core GEMM, fp16 output)
    {
        cudaFuncSetAttribute(gemmY_kernel,
                             cudaFuncAttributeMaxDynamicSharedMemorySize, SMEM_TOTAL);
        gemmY_kernel<<<296, 256, SMEM_TOTAL>>>(x, n_nodes);
    }
    // 6) out = aggregate(Y)
    agg_kernel<<<(n_nodes + 7) / 8, 256>>>(out, n_nodes);
}